// round 3
// baseline (speedup 1.0000x reference)
#include <cuda_runtime.h>
#include <cstdint>

#define N_NODES 50000
#define HIDDEN  64
#define INDIM   512
#define OUTDIM  40

// Scratch (device globals: no allocation allowed in kernel_launch)
__device__ __align__(16) float g_h[N_NODES * HIDDEN];     // X @ W1
__device__ __align__(16) float g_agg[N_NODES * HIDDEN];   // aggregated messages
__device__ __align__(16) float g_deg[N_NODES];
__device__ __align__(16) float g_dinv[N_NODES];

// ---------------------------------------------------------------------------
// Degree: deg[i] = 1 (self loop) + #edges with dst==i
// ---------------------------------------------------------------------------
__global__ void init_deg_kernel(int n) {
    int i = blockIdx.x * blockDim.x + threadIdx.x;
    if (i < n) g_deg[i] = 1.0f;
}

__global__ void deg_accum_kernel(const int* __restrict__ dst, int E, int n) {
    int e = blockIdx.x * blockDim.x + threadIdx.x;
    if (e < E) {
        int d = dst[e];
        if ((unsigned)d < (unsigned)n) atomicAdd(&g_deg[d], 1.0f);
    }
}

// ---------------------------------------------------------------------------
// GEMM1: g_h[n,64] = X[n,512] @ W1[512,64]
// 64x64 block tile, BK=32, 256 threads, 4x4 micro-tile per thread.
// ---------------------------------------------------------------------------
__global__ __launch_bounds__(256) void gemm1_kernel(
    const float* __restrict__ X, const float* __restrict__ W, int n)
{
    __shared__ float Xs[32 * 68];  // [k][row], padded stride 68
    __shared__ float Ws[32 * 64];  // [k][col]

    const int tid = threadIdx.x;
    const int tr = tid >> 4;       // 0..15 (row group of 4)
    const int tc = tid & 15;       // 0..15 (col group of 4)
    const int row0 = blockIdx.x * 64;

    float acc[4][4] = {};

    for (int k0 = 0; k0 < INDIM; k0 += 32) {
        // Load X tile 64 rows x 32 k, transposed into Xs[k][row]
        #pragma unroll
        for (int t = 0; t < 2; t++) {
            int s = t * 256 + tid;        // 0..511 float4 slots
            int r = s >> 3, q = s & 7;    // row, k-quad
            int rr = row0 + r; if (rr >= n) rr = n - 1;
            float4 v = *(const float4*)(X + (size_t)rr * INDIM + k0 + q * 4);
            Xs[(q * 4 + 0) * 68 + r] = v.x;
            Xs[(q * 4 + 1) * 68 + r] = v.y;
            Xs[(q * 4 + 2) * 68 + r] = v.z;
            Xs[(q * 4 + 3) * 68 + r] = v.w;
        }
        // Load W tile 32 k x 64 cols
        #pragma unroll
        for (int t = 0; t < 2; t++) {
            int s = t * 256 + tid;
            int kk = s >> 4, q = s & 15;
            *(float4*)(Ws + kk * 64 + q * 4) =
                *(const float4*)(W + (size_t)(k0 + kk) * HIDDEN + q * 4);
        }
        __syncthreads();

        #pragma unroll
        for (int kk = 0; kk < 32; kk++) {
            float4 xv = *(const float4*)(Xs + kk * 68 + tr * 4);
            float4 wv = *(const float4*)(Ws + kk * 64 + tc * 4);
            float xs[4] = {xv.x, xv.y, xv.z, xv.w};
            float ws[4] = {wv.x, wv.y, wv.z, wv.w};
            #pragma unroll
            for (int i = 0; i < 4; i++)
                #pragma unroll
                for (int j = 0; j < 4; j++)
                    acc[i][j] += xs[i] * ws[j];
        }
        __syncthreads();
    }

    #pragma unroll
    for (int i = 0; i < 4; i++) {
        int row = row0 + tr * 4 + i;
        if (row < n) {
            float4 o = make_float4(acc[i][0], acc[i][1], acc[i][2], acc[i][3]);
            *(float4*)(g_h + (size_t)row * HIDDEN + tc * 4) = o;
        }
    }
}

// ---------------------------------------------------------------------------
// dinv = rsqrt(deg);  agg[i,:] = dinv[i]^2 * h[i,:]   (self-loop contribution)
// ---------------------------------------------------------------------------
__global__ void selfloop_kernel(int n) {
    int idx = blockIdx.x * blockDim.x + threadIdx.x;
    if (idx >= n * 16) return;
    int i = idx >> 4, q = idx & 15;
    float d = rsqrtf(g_deg[i]);
    if (q == 0) g_dinv[i] = d;
    float c = d * d;
    float4 v = ((const float4*)g_h)[idx];
    v.x *= c; v.y *= c; v.z *= c; v.w *= c;
    ((float4*)g_agg)[idx] = v;
}

// ---------------------------------------------------------------------------
// Edge scatter: agg[dst,:] += dinv[src]*dinv[dst] * h[src,:]
// 16 threads per edge; float4 gather, 4 scalar L2 reductions each.
// ---------------------------------------------------------------------------
__global__ void scatter_kernel(const int* __restrict__ src,
                               const int* __restrict__ dst, int E, int n)
{
    int idx = blockIdx.x * blockDim.x + threadIdx.x;
    if (idx >= E * 16) return;
    int e = idx >> 4, q = idx & 15;
    int s = src[e];
    int d = dst[e];
    if ((unsigned)s >= (unsigned)n || (unsigned)d >= (unsigned)n) return;
    float coef = g_dinv[s] * g_dinv[d];
    float4 v = ((const float4*)g_h)[s * 16 + q];
    float* base = g_agg + (size_t)d * HIDDEN + q * 4;
    atomicAdd(base + 0, coef * v.x);
    atomicAdd(base + 1, coef * v.y);
    atomicAdd(base + 2, coef * v.z);
    atomicAdd(base + 3, coef * v.w);
}

// ---------------------------------------------------------------------------
// GEMM2: out[n,40] = relu(agg + b1) @ Wfc^T + bfc
// Block: 24 rows, blockDim (10,24) = 240 threads; each thread -> 1 row x 4 outs.
// ---------------------------------------------------------------------------
__global__ __launch_bounds__(240) void gemm2_kernel(
    const float* __restrict__ b1, const float* __restrict__ Wfc,
    const float* __restrict__ bfc, float* __restrict__ out, int n)
{
    __shared__ float hs[24 * 68];   // [row][j], padded stride 68
    __shared__ float Wt[64 * 40];   // [j][o]  (transposed Wfc)
    __shared__ float bfs[40];

    const int tx = threadIdx.x;     // 0..9  (output quad)
    const int ty = threadIdx.y;     // 0..23 (row)
    const int tid = ty * 10 + tx;

    for (int idx = tid; idx < 64 * 40; idx += 240) {
        int o = idx % 40, j = idx / 40;
        Wt[j * 40 + o] = Wfc[o * 64 + j];
    }
    if (tid < 40) bfs[tid] = bfc[tid];

    const int row0 = blockIdx.x * 24;
    for (int idx = tid; idx < 24 * 16; idx += 240) {
        int r = idx >> 4, q = idx & 15;
        int grow = row0 + r;
        float4 v = make_float4(0.f, 0.f, 0.f, 0.f);
        if (grow < n) {
            v = ((const float4*)g_agg)[grow * 16 + q];
            float4 bb = ((const float4*)b1)[q];
            v.x = fmaxf(v.x + bb.x, 0.f);
            v.y = fmaxf(v.y + bb.y, 0.f);
            v.z = fmaxf(v.z + bb.z, 0.f);
            v.w = fmaxf(v.w + bb.w, 0.f);
        }
        *(float4*)(hs + r * 68 + q * 4) = v;
    }
    __syncthreads();

    float4 acc = make_float4(0.f, 0.f, 0.f, 0.f);
    #pragma unroll
    for (int j = 0; j < 64; j++) {
        float h = hs[ty * 68 + j];
        float4 w = *(const float4*)(Wt + j * 40 + tx * 4);
        acc.x += h * w.x;
        acc.y += h * w.y;
        acc.z += h * w.z;
        acc.w += h * w.w;
    }

    int grow = row0 + ty;
    if (grow < n) {
        float4 bb = *(const float4*)(bfs + tx * 4);
        acc.x += bb.x; acc.y += bb.y; acc.z += bb.z; acc.w += bb.w;
        *(float4*)(out + (size_t)grow * OUTDIM + tx * 4) = acc;
    }
}

// ---------------------------------------------------------------------------
extern "C" void kernel_launch(void* const* d_in, const int* in_sizes, int n_in,
                              void* d_out, int out_size)
{
    const float* X     = (const float*)d_in[0];
    const int*   edges = (const int*)d_in[1];     // int64 downcast to int32 by harness
    const float* W1    = (const float*)d_in[2];
    const float* b1    = (const float*)d_in[3];
    const float* Wfc   = (const float*)d_in[4];
    const float* bfc   = (const float*)d_in[5];
    float* out = (float*)d_out;

    const int n = in_sizes[0] / INDIM;
    const int E = in_sizes[1] / 2;
    const int* src = edges;
    const int* dst = edges + E;

    init_deg_kernel<<<(n + 255) / 256, 256>>>(n);
    deg_accum_kernel<<<(E + 255) / 256, 256>>>(dst, E, n);
    gemm1_kernel<<<(n + 63) / 64, 256>>>(X, W1, n);
    selfloop_kernel<<<(n * 16 + 255) / 256, 256>>>(n);
    scatter_kernel<<<(E * 16 + 255) / 256, 256>>>(src, dst, E, n);
    gemm2_kernel<<<(n + 23) / 24, dim3(10, 24)>>>(b1, Wfc, bfc, out, n);
}

// round 4
// speedup vs baseline: 1.2471x; 1.2471x over previous
#include <cuda_runtime.h>
#include <cstdint>

#define N_NODES 50000
#define HIDDEN  64
#define INDIM   512
#define OUTDIM  40

// Scratch (device globals: no allocation allowed in kernel_launch)
__device__ __align__(16) float g_h[N_NODES * HIDDEN];     // X @ W1
__device__ __align__(16) float g_hs[N_NODES * HIDDEN];    // dinv[i] * h[i]
__device__ __align__(16) float g_agg[N_NODES * HIDDEN];   // aggregated messages
__device__ __align__(16) float g_deg[N_NODES];
__device__ __align__(16) float g_dinv[N_NODES];

// ---------------------------------------------------------------------------
// Degree: deg[i] = 1 (self loop) + #edges with dst==i
// ---------------------------------------------------------------------------
__global__ void init_deg_kernel(int n) {
    int i = blockIdx.x * blockDim.x + threadIdx.x;
    if (i < n) g_deg[i] = 1.0f;
}

__global__ void deg_accum_kernel(const int* __restrict__ dst, int E, int n) {
    int e = blockIdx.x * blockDim.x + threadIdx.x;
    if (e < E) {
        int d = dst[e];
        if ((unsigned)d < (unsigned)n) atomicAdd(&g_deg[d], 1.0f);
    }
}

// ---------------------------------------------------------------------------
// GEMM1: g_h[n,64] = X[n,512] @ W1[512,64]
// 64x64 block tile, BK=32, 256 threads, 4x4 micro-tile per thread.
// ---------------------------------------------------------------------------
__global__ __launch_bounds__(256) void gemm1_kernel(
    const float* __restrict__ X, const float* __restrict__ W, int n)
{
    __shared__ float Xs[32 * 68];  // [k][row], padded stride 68
    __shared__ float Ws[32 * 64];  // [k][col]

    const int tid = threadIdx.x;
    const int tr = tid >> 4;       // 0..15 (row group of 4)
    const int tc = tid & 15;       // 0..15 (col group of 4)
    const int row0 = blockIdx.x * 64;

    float acc[4][4] = {};

    for (int k0 = 0; k0 < INDIM; k0 += 32) {
        // Load X tile 64 rows x 32 k, transposed into Xs[k][row]
        #pragma unroll
        for (int t = 0; t < 2; t++) {
            int s = t * 256 + tid;        // 0..511 float4 slots
            int r = s >> 3, q = s & 7;    // row, k-quad
            int rr = row0 + r; if (rr >= n) rr = n - 1;
            float4 v = *(const float4*)(X + (size_t)rr * INDIM + k0 + q * 4);
            Xs[(q * 4 + 0) * 68 + r] = v.x;
            Xs[(q * 4 + 1) * 68 + r] = v.y;
            Xs[(q * 4 + 2) * 68 + r] = v.z;
            Xs[(q * 4 + 3) * 68 + r] = v.w;
        }
        // Load W tile 32 k x 64 cols
        #pragma unroll
        for (int t = 0; t < 2; t++) {
            int s = t * 256 + tid;
            int kk = s >> 4, q = s & 15;
            *(float4*)(Ws + kk * 64 + q * 4) =
                *(const float4*)(W + (size_t)(k0 + kk) * HIDDEN + q * 4);
        }
        __syncthreads();

        #pragma unroll
        for (int kk = 0; kk < 32; kk++) {
            float4 xv = *(const float4*)(Xs + kk * 68 + tr * 4);
            float4 wv = *(const float4*)(Ws + kk * 64 + tc * 4);
            float xs[4] = {xv.x, xv.y, xv.z, xv.w};
            float ws[4] = {wv.x, wv.y, wv.z, wv.w};
            #pragma unroll
            for (int i = 0; i < 4; i++)
                #pragma unroll
                for (int j = 0; j < 4; j++)
                    acc[i][j] += xs[i] * ws[j];
        }
        __syncthreads();
    }

    #pragma unroll
    for (int i = 0; i < 4; i++) {
        int row = row0 + tr * 4 + i;
        if (row < n) {
            float4 o = make_float4(acc[i][0], acc[i][1], acc[i][2], acc[i][3]);
            *(float4*)(g_h + (size_t)row * HIDDEN + tc * 4) = o;
        }
    }
}

// ---------------------------------------------------------------------------
// dinv = rsqrt(deg); g_hs[i,:] = dinv*h; agg[i,:] = dinv^2*h (self-loop term)
// ---------------------------------------------------------------------------
__global__ void selfloop_kernel(int n) {
    int idx = blockIdx.x * blockDim.x + threadIdx.x;
    if (idx >= n * 16) return;
    int i = idx >> 4, q = idx & 15;
    float d = rsqrtf(g_deg[i]);
    if (q == 0) g_dinv[i] = d;
    float4 v = ((const float4*)g_h)[idx];
    float4 s = make_float4(d * v.x, d * v.y, d * v.z, d * v.w);
    ((float4*)g_hs)[idx] = s;
    float4 a = make_float4(d * s.x, d * s.y, d * s.z, d * s.w);
    ((float4*)g_agg)[idx] = a;
}

// ---------------------------------------------------------------------------
// Edge scatter: agg[dst,:] += dinv[dst] * g_hs[src,:]
// 16 threads per edge; float4 gather, one v4 L2 reduction each.
// ---------------------------------------------------------------------------
__device__ __forceinline__ void red_add_v4(float* addr, float4 v) {
    asm volatile("red.global.add.v4.f32 [%0], {%1, %2, %3, %4};"
                 :: "l"(__cvta_generic_to_global(addr)),
                    "f"(v.x), "f"(v.y), "f"(v.z), "f"(v.w)
                 : "memory");
}

__global__ void scatter_kernel(const int* __restrict__ src,
                               const int* __restrict__ dst, int E, int n)
{
    int idx = blockIdx.x * blockDim.x + threadIdx.x;
    if (idx >= E * 16) return;
    int e = idx >> 4, q = idx & 15;
    int s = src[e];
    int d = dst[e];
    if ((unsigned)s >= (unsigned)n || (unsigned)d >= (unsigned)n) return;
    float coef = g_dinv[d];
    float4 v = ((const float4*)g_hs)[s * 16 + q];
    v.x *= coef; v.y *= coef; v.z *= coef; v.w *= coef;
    red_add_v4(g_agg + (size_t)d * HIDDEN + q * 4, v);
}

// ---------------------------------------------------------------------------
// GEMM2: out[n,40] = relu(agg + b1) @ Wfc^T + bfc
// Block: 24 rows, blockDim (10,24) = 240 threads; each thread -> 1 row x 4 outs.
// ---------------------------------------------------------------------------
__global__ __launch_bounds__(240) void gemm2_kernel(
    const float* __restrict__ b1, const float* __restrict__ Wfc,
    const float* __restrict__ bfc, float* __restrict__ out, int n)
{
    __shared__ float hs[24 * 68];   // [row][j], padded stride 68
    __shared__ float Wt[64 * 40];   // [j][o]  (transposed Wfc)
    __shared__ float bfs[40];

    const int tx = threadIdx.x;     // 0..9  (output quad)
    const int ty = threadIdx.y;     // 0..23 (row)
    const int tid = ty * 10 + tx;

    for (int idx = tid; idx < 64 * 40; idx += 240) {
        int o = idx % 40, j = idx / 40;
        Wt[j * 40 + o] = Wfc[o * 64 + j];
    }
    if (tid < 40) bfs[tid] = bfc[tid];

    const int row0 = blockIdx.x * 24;
    for (int idx = tid; idx < 24 * 16; idx += 240) {
        int r = idx >> 4, q = idx & 15;
        int grow = row0 + r;
        float4 v = make_float4(0.f, 0.f, 0.f, 0.f);
        if (grow < n) {
            v = ((const float4*)g_agg)[grow * 16 + q];
            float4 bb = ((const float4*)b1)[q];
            v.x = fmaxf(v.x + bb.x, 0.f);
            v.y = fmaxf(v.y + bb.y, 0.f);
            v.z = fmaxf(v.z + bb.z, 0.f);
            v.w = fmaxf(v.w + bb.w, 0.f);
        }
        *(float4*)(hs + r * 68 + q * 4) = v;
    }
    __syncthreads();

    float4 acc = make_float4(0.f, 0.f, 0.f, 0.f);
    #pragma unroll
    for (int j = 0; j < 64; j++) {
        float h = hs[ty * 68 + j];
        float4 w = *(const float4*)(Wt + j * 40 + tx * 4);
        acc.x += h * w.x;
        acc.y += h * w.y;
        acc.z += h * w.z;
        acc.w += h * w.w;
    }

    int grow = row0 + ty;
    if (grow < n) {
        float4 bb = *(const float4*)(bfs + tx * 4);
        acc.x += bb.x; acc.y += bb.y; acc.z += bb.z; acc.w += bb.w;
        *(float4*)(out + (size_t)grow * OUTDIM + tx * 4) = acc;
    }
}

// ---------------------------------------------------------------------------
extern "C" void kernel_launch(void* const* d_in, const int* in_sizes, int n_in,
                              void* d_out, int out_size)
{
    const float* X     = (const float*)d_in[0];
    const int*   edges = (const int*)d_in[1];     // int64 downcast to int32 by harness
    const float* W1    = (const float*)d_in[2];
    const float* b1    = (const float*)d_in[3];
    const float* Wfc   = (const float*)d_in[4];
    const float* bfc   = (const float*)d_in[5];
    float* out = (float*)d_out;

    const int n = in_sizes[0] / INDIM;
    const int E = in_sizes[1] / 2;
    const int* src = edges;
    const int* dst = edges + E;

    init_deg_kernel<<<(n + 255) / 256, 256>>>(n);
    deg_accum_kernel<<<(E + 255) / 256, 256>>>(dst, E, n);
    gemm1_kernel<<<(n + 63) / 64, 256>>>(X, W1, n);
    selfloop_kernel<<<(n * 16 + 255) / 256, 256>>>(n);
    scatter_kernel<<<(E * 16 + 255) / 256, 256>>>(src, dst, E, n);
    gemm2_kernel<<<(n + 23) / 24, dim3(10, 24)>>>(b1, Wfc, bfc, out, n);
}

// round 5
// speedup vs baseline: 1.7218x; 1.3807x over previous
#include <cuda_runtime.h>
#include <cstdint>

#define N_NODES 50000
#define HIDDEN  64
#define INDIM   512
#define OUTDIM  40

// Scratch (device globals: no allocation allowed in kernel_launch)
__device__ __align__(16) float g_h[N_NODES * HIDDEN];     // X @ W1
__device__ __align__(16) float g_hs[N_NODES * HIDDEN];    // dinv[i] * h[i]
__device__ __align__(16) float g_agg[N_NODES * HIDDEN];   // aggregated messages
__device__ __align__(16) float g_deg[N_NODES];
__device__ __align__(16) float g_dinv[N_NODES];

// ---------------------------------------------------------------------------
// Degree: deg[i] = 1 (self loop) + #edges with dst==i
// ---------------------------------------------------------------------------
__global__ void init_deg_kernel(int n) {
    int i = blockIdx.x * blockDim.x + threadIdx.x;
    if (i < n) g_deg[i] = 1.0f;
}

__global__ void deg_accum_kernel(const int* __restrict__ dst, int E, int n) {
    int e = blockIdx.x * blockDim.x + threadIdx.x;
    if (e < E) {
        int d = dst[e];
        if ((unsigned)d < (unsigned)n) atomicAdd(&g_deg[d], 1.0f);
    }
}

// ---------------------------------------------------------------------------
// GEMM1 (tensor cores, tf32): g_h[n,64] = X[n,512] @ W1[512,64]
// 128-row block, 8 warps; warp = 16 rows x 64 cols via mma.m16n8k8.tf32.
// ---------------------------------------------------------------------------
__device__ __forceinline__ uint32_t f2tf32(float f) {
    uint32_t r;
    asm("cvt.rna.tf32.f32 %0, %1;" : "=r"(r) : "f"(f));
    return r;
}

#define XS_STRIDE 36   // banks for A frag: 4*gid + tig -> conflict-free
#define WS_STRIDE 72   // banks for B frag: 8*row + col -> conflict-free

__global__ __launch_bounds__(256) void gemm1_mma_kernel(
    const float* __restrict__ X, const float* __restrict__ W, int n)
{
    __shared__ uint32_t Xs[128 * XS_STRIDE];
    __shared__ uint32_t Ws[32 * WS_STRIDE];

    const int tid  = threadIdx.x;
    const int lane = tid & 31;
    const int wid  = tid >> 5;        // 0..7
    const int gid  = lane >> 2;       // 0..7
    const int tig  = lane & 3;        // 0..3
    const int wrow = wid * 16;
    const int row0 = blockIdx.x * 128;

    float acc[8][4] = {};

    for (int k0 = 0; k0 < INDIM; k0 += 32) {
        // X tile: 128 rows x 32 k  (1024 float4 slots / 256 threads = 4 each)
        #pragma unroll
        for (int t = 0; t < 4; t++) {
            int s = t * 256 + tid;
            int r = s >> 3, q = s & 7;
            int rr = row0 + r; if (rr >= n) rr = n - 1;
            float4 v = *(const float4*)(X + (size_t)rr * INDIM + k0 + q * 4);
            uint32_t* p = Xs + r * XS_STRIDE + q * 4;
            p[0] = f2tf32(v.x); p[1] = f2tf32(v.y);
            p[2] = f2tf32(v.z); p[3] = f2tf32(v.w);
        }
        // W tile: 32 k x 64 cols (512 float4 / 256 threads = 2 each)
        #pragma unroll
        for (int t = 0; t < 2; t++) {
            int s = t * 256 + tid;
            int kk = s >> 4, q = s & 15;
            float4 v = *(const float4*)(W + (size_t)(k0 + kk) * HIDDEN + q * 4);
            uint32_t* p = Ws + kk * WS_STRIDE + q * 4;
            p[0] = f2tf32(v.x); p[1] = f2tf32(v.y);
            p[2] = f2tf32(v.z); p[3] = f2tf32(v.w);
        }
        __syncthreads();

        #pragma unroll
        for (int kk = 0; kk < 32; kk += 8) {
            uint32_t a0 = Xs[(wrow + gid) * XS_STRIDE + kk + tig];
            uint32_t a1 = Xs[(wrow + gid + 8) * XS_STRIDE + kk + tig];
            uint32_t a2 = Xs[(wrow + gid) * XS_STRIDE + kk + tig + 4];
            uint32_t a3 = Xs[(wrow + gid + 8) * XS_STRIDE + kk + tig + 4];
            #pragma unroll
            for (int nb = 0; nb < 8; nb++) {
                uint32_t b0 = Ws[(kk + tig) * WS_STRIDE + nb * 8 + gid];
                uint32_t b1 = Ws[(kk + tig + 4) * WS_STRIDE + nb * 8 + gid];
                asm volatile(
                    "mma.sync.aligned.m16n8k8.row.col.f32.tf32.tf32.f32 "
                    "{%0,%1,%2,%3}, {%4,%5,%6,%7}, {%8,%9}, {%0,%1,%2,%3};"
                    : "+f"(acc[nb][0]), "+f"(acc[nb][1]),
                      "+f"(acc[nb][2]), "+f"(acc[nb][3])
                    : "r"(a0), "r"(a1), "r"(a2), "r"(a3), "r"(b0), "r"(b1));
            }
        }
        __syncthreads();
    }

    // Epilogue: c0,c1 at (row, col..col+1); c2,c3 at (row+8, ...)
    const int rA = row0 + wrow + gid;
    const int rB = rA + 8;
    #pragma unroll
    for (int nb = 0; nb < 8; nb++) {
        int col = nb * 8 + 2 * tig;
        if (rA < n)
            *(float2*)(g_h + (size_t)rA * HIDDEN + col) =
                make_float2(acc[nb][0], acc[nb][1]);
        if (rB < n)
            *(float2*)(g_h + (size_t)rB * HIDDEN + col) =
                make_float2(acc[nb][2], acc[nb][3]);
    }
}

// ---------------------------------------------------------------------------
// dinv = rsqrt(deg); g_hs[i,:] = dinv*h; agg[i,:] = dinv^2*h (self-loop term)
// ---------------------------------------------------------------------------
__global__ void selfloop_kernel(int n) {
    int idx = blockIdx.x * blockDim.x + threadIdx.x;
    if (idx >= n * 16) return;
    int i = idx >> 4, q = idx & 15;
    float d = rsqrtf(g_deg[i]);
    if (q == 0) g_dinv[i] = d;
    float4 v = ((const float4*)g_h)[idx];
    float4 s = make_float4(d * v.x, d * v.y, d * v.z, d * v.w);
    ((float4*)g_hs)[idx] = s;
    float4 a = make_float4(d * s.x, d * s.y, d * s.z, d * s.w);
    ((float4*)g_agg)[idx] = a;
}

// ---------------------------------------------------------------------------
// Edge scatter: agg[dst,:] += dinv[dst] * g_hs[src,:]
// 16 threads per edge; float4 gather, one v4 L2 reduction each.
// ---------------------------------------------------------------------------
__device__ __forceinline__ void red_add_v4(float* addr, float4 v) {
    asm volatile("red.global.add.v4.f32 [%0], {%1, %2, %3, %4};"
                 :: "l"(__cvta_generic_to_global(addr)),
                    "f"(v.x), "f"(v.y), "f"(v.z), "f"(v.w)
                 : "memory");
}

__global__ void scatter_kernel(const int* __restrict__ src,
                               const int* __restrict__ dst, int E, int n)
{
    int idx = blockIdx.x * blockDim.x + threadIdx.x;
    if (idx >= E * 16) return;
    int e = idx >> 4, q = idx & 15;
    int s = src[e];
    int d = dst[e];
    if ((unsigned)s >= (unsigned)n || (unsigned)d >= (unsigned)n) return;
    float coef = g_dinv[d];
    float4 v = ((const float4*)g_hs)[s * 16 + q];
    v.x *= coef; v.y *= coef; v.z *= coef; v.w *= coef;
    red_add_v4(g_agg + (size_t)d * HIDDEN + q * 4, v);
}

// ---------------------------------------------------------------------------
// GEMM2: out[n,40] = relu(agg + b1) @ Wfc^T + bfc
// ---------------------------------------------------------------------------
__global__ __launch_bounds__(240) void gemm2_kernel(
    const float* __restrict__ b1, const float* __restrict__ Wfc,
    const float* __restrict__ bfc, float* __restrict__ out, int n)
{
    __shared__ float hs[24 * 68];
    __shared__ float Wt[64 * 40];
    __shared__ float bfs[40];

    const int tx = threadIdx.x;     // 0..9
    const int ty = threadIdx.y;     // 0..23
    const int tid = ty * 10 + tx;

    for (int idx = tid; idx < 64 * 40; idx += 240) {
        int o = idx % 40, j = idx / 40;
        Wt[j * 40 + o] = Wfc[o * 64 + j];
    }
    if (tid < 40) bfs[tid] = bfc[tid];

    const int row0 = blockIdx.x * 24;
    for (int idx = tid; idx < 24 * 16; idx += 240) {
        int r = idx >> 4, q = idx & 15;
        int grow = row0 + r;
        float4 v = make_float4(0.f, 0.f, 0.f, 0.f);
        if (grow < n) {
            v = ((const float4*)g_agg)[grow * 16 + q];
            float4 bb = ((const float4*)b1)[q];
            v.x = fmaxf(v.x + bb.x, 0.f);
            v.y = fmaxf(v.y + bb.y, 0.f);
            v.z = fmaxf(v.z + bb.z, 0.f);
            v.w = fmaxf(v.w + bb.w, 0.f);
        }
        *(float4*)(hs + r * 68 + q * 4) = v;
    }
    __syncthreads();

    float4 acc = make_float4(0.f, 0.f, 0.f, 0.f);
    #pragma unroll
    for (int j = 0; j < 64; j++) {
        float h = hs[ty * 68 + j];
        float4 w = *(const float4*)(Wt + j * 40 + tx * 4);
        acc.x += h * w.x;
        acc.y += h * w.y;
        acc.z += h * w.z;
        acc.w += h * w.w;
    }

    int grow = row0 + ty;
    if (grow < n) {
        float4 bb = *(const float4*)(bfs + tx * 4);
        acc.x += bb.x; acc.y += bb.y; acc.z += bb.z; acc.w += bb.w;
        *(float4*)(out + (size_t)grow * OUTDIM + tx * 4) = acc;
    }
}

// ---------------------------------------------------------------------------
extern "C" void kernel_launch(void* const* d_in, const int* in_sizes, int n_in,
                              void* d_out, int out_size)
{
    const float* X     = (const float*)d_in[0];
    const int*   edges = (const int*)d_in[1];     // int64 downcast to int32 by harness
    const float* W1    = (const float*)d_in[2];
    const float* b1    = (const float*)d_in[3];
    const float* Wfc   = (const float*)d_in[4];
    const float* bfc   = (const float*)d_in[5];
    float* out = (float*)d_out;

    const int n = in_sizes[0] / INDIM;
    const int E = in_sizes[1] / 2;
    const int* src = edges;
    const int* dst = edges + E;

    init_deg_kernel<<<(n + 255) / 256, 256>>>(n);
    deg_accum_kernel<<<(E + 255) / 256, 256>>>(dst, E, n);
    gemm1_mma_kernel<<<(n + 127) / 128, 256>>>(X, W1, n);
    selfloop_kernel<<<(n * 16 + 255) / 256, 256>>>(n);
    scatter_kernel<<<(E * 16 + 255) / 256, 256>>>(src, dst, E, n);
    gemm2_kernel<<<(n + 23) / 24, dim3(10, 24)>>>(b1, Wfc, bfc, out, n);
}